// round 2
// baseline (speedup 1.0000x reference)
#include <cuda_runtime.h>
#include <cstdint>
#include <math.h>

#define T_ 1024
#define H_ 2048
#define E_ 64
#define K_ 8
#define I_ 1024
#define NSLOT (T_*K_)

// ---------------- scratch (device globals; no allocation allowed) ----------------
__device__ float g_logits[T_*E_];
__device__ int   g_topk_idx[NSLOT];
__device__ float g_topk_wt[NSLOT];
__device__ int   g_cnt[E_];
__device__ int   g_off[E_];
__device__ int   g_cur[E_];
__device__ int   g_tok[NSLOT + 128];
__device__ float g_wt[NSLOT + 128];
__device__ float g_act[(size_t)(NSLOT + 128) * I_];   // ~34 MB

// ---------------- helpers ----------------
__device__ __forceinline__ uint32_t f2tf(float x) {
    uint32_t r;
    asm("cvt.rna.tf32.f32 %0, %1;" : "=r"(r) : "f"(x));
    return r;
}

__device__ __forceinline__ void mma_tf32(float d[4],
    uint32_t a0, uint32_t a1, uint32_t a2, uint32_t a3,
    uint32_t b0, uint32_t b1)
{
    asm volatile(
        "mma.sync.aligned.m16n8k8.row.col.f32.tf32.tf32.f32 "
        "{%0,%1,%2,%3}, {%4,%5,%6,%7}, {%8,%9}, {%0,%1,%2,%3};\n"
        : "+f"(d[0]), "+f"(d[1]), "+f"(d[2]), "+f"(d[3])
        : "r"(a0), "r"(a1), "r"(a2), "r"(a3), "r"(b0), "r"(b1));
}

// ---------------- 0: zero output + counters ----------------
__global__ void k_zero(float* __restrict__ out) {
    int i = blockIdx.x * blockDim.x + threadIdx.x;
    if (i < T_*H_) out[i] = 0.f;
    if (i < E_) { g_cnt[i] = 0; g_cur[i] = 0; }
}

// ---------------- 1: router logits (fp32, exactness matters for top-k) ----------------
// block = 256 threads handles 4 tokens; warp w covers experts [8w, 8w+8)
__global__ void __launch_bounds__(256) k_router(const float* __restrict__ x,
                                                const float* __restrict__ gw) {
    __shared__ float xs[4 * H_];
    int t0 = blockIdx.x * 4;
    for (int i = threadIdx.x; i < 4 * H_; i += 256)
        xs[i] = x[(size_t)t0 * H_ + i];
    __syncthreads();
    int warp = threadIdx.x >> 5, lane = threadIdx.x & 31;
    for (int ei = 0; ei < 8; ei++) {
        int e = warp * 8 + ei;
        const float* w = gw + (size_t)e * H_;
        float a0 = 0.f, a1 = 0.f, a2 = 0.f, a3 = 0.f;
        for (int h = lane; h < H_; h += 32) {
            float wv = w[h];
            a0 = fmaf(wv, xs[h],          a0);
            a1 = fmaf(wv, xs[H_   + h],   a1);
            a2 = fmaf(wv, xs[2*H_ + h],   a2);
            a3 = fmaf(wv, xs[3*H_ + h],   a3);
        }
        #pragma unroll
        for (int o = 16; o; o >>= 1) {
            a0 += __shfl_xor_sync(0xffffffffu, a0, o);
            a1 += __shfl_xor_sync(0xffffffffu, a1, o);
            a2 += __shfl_xor_sync(0xffffffffu, a2, o);
            a3 += __shfl_xor_sync(0xffffffffu, a3, o);
        }
        if (lane == 0) {
            g_logits[(t0+0)*E_ + e] = a0;
            g_logits[(t0+1)*E_ + e] = a1;
            g_logits[(t0+2)*E_ + e] = a2;
            g_logits[(t0+3)*E_ + e] = a3;
        }
    }
}

// ---------------- 2: softmax + top-8 per token + expert histogram ----------------
__global__ void k_topk() {
    int t = blockIdx.x * blockDim.x + threadIdx.x;
    if (t >= T_) return;
    float l[E_];
    const float* lg = g_logits + t * E_;
    float mx = -1e30f;
    for (int e = 0; e < E_; e++) { l[e] = lg[e]; mx = fmaxf(mx, l[e]); }
    float s = 0.f;
    for (int e = 0; e < E_; e++) { l[e] = expf(l[e] - mx); s += l[e]; }
    float inv = 1.f / s;
    for (int k = 0; k < K_; k++) {
        float best = -1.f; int be = 0;
        for (int e = 0; e < E_; e++)
            if (l[e] > best) { best = l[e]; be = e; }   // strict > => lowest index on ties (matches top_k)
        g_topk_idx[t*K_ + k] = be;
        g_topk_wt [t*K_ + k] = best * inv;
        l[be] = -1.f;
        atomicAdd(&g_cnt[be], 1);
    }
}

// ---------------- 3: exclusive scan over 64 counts ----------------
__global__ void k_scan() {
    if (threadIdx.x == 0) {
        int acc = 0;
        for (int e = 0; e < E_; e++) { g_off[e] = acc; acc += g_cnt[e]; }
    }
}

// ---------------- 4: fill per-expert slot lists ----------------
__global__ void k_fill() {
    int i = blockIdx.x * blockDim.x + threadIdx.x;
    if (i >= NSLOT) return;
    int t = i >> 3;            // K_ = 8
    int e = g_topk_idx[i];
    int pos = atomicAdd(&g_cur[e], 1);
    int slot = g_off[e] + pos;
    g_tok[slot] = t;
    g_wt [slot] = g_topk_wt[i];
}

// ---------------- 5: grouped gate/up GEMM + SiLU (tf32 mma) ----------------
// Block tile: M=64 (gathered tokens) x N=64 (intermediate cols), K chunk=32.
// 8 warps: 4 along M x 2 along N; each warp = 16x32 region for BOTH gate & up.
__global__ void __launch_bounds__(256) k_gateup(const float* __restrict__ x,
                                                const float* __restrict__ wg,
                                                const float* __restrict__ wu) {
    int e  = blockIdx.z;
    int cnt = g_cnt[e];
    int mt = blockIdx.y;
    if (mt * 64 >= cnt) return;
    int i0 = blockIdx.x * 64;
    int slot0 = g_off[e] + mt * 64;
    int valid = cnt - mt * 64; if (valid > 64) valid = 64;

    __shared__ float sA[64 * 36];
    __shared__ float sG[32 * 68];
    __shared__ float sU[32 * 68];

    int tid  = threadIdx.x;
    int lane = tid & 31, warp = tid >> 5;
    int wm = warp >> 1, wn = warp & 1;
    int ln4 = lane >> 2, lc = lane & 3;

    // per-thread load descriptors (2 float4 per tile per matrix)
    const float* aptr[2]; int arow[2], acol[2];
    const float* gptr[2]; const float* uptr[2]; int brow[2], bcol[2];
    #pragma unroll
    for (int r = 0; r < 2; r++) {
        int idx = tid + r * 256;
        int rowa = idx >> 3, c4a = idx & 7;
        int tok = (rowa < valid) ? g_tok[slot0 + rowa] : g_tok[slot0];
        aptr[r] = x + (size_t)tok * H_ + c4a * 4;
        arow[r] = rowa; acol[r] = c4a * 4;
        int rowb = idx >> 4, c4b = idx & 15;
        brow[r] = rowb; bcol[r] = c4b * 4;
        gptr[r] = wg + ((size_t)e * H_ + rowb) * I_ + i0 + c4b * 4;
        uptr[r] = wu + ((size_t)e * H_ + rowb) * I_ + i0 + c4b * 4;
    }

    float cg[4][4], cu[4][4];
    #pragma unroll
    for (int f = 0; f < 4; f++)
        #pragma unroll
        for (int j = 0; j < 4; j++) { cg[f][j] = 0.f; cu[f][j] = 0.f; }

    float4 va[2], vg[2], vu[2];
    #pragma unroll
    for (int r = 0; r < 2; r++) {
        va[r] = *(const float4*)(aptr[r]);
        vg[r] = *(const float4*)(gptr[r]);
        vu[r] = *(const float4*)(uptr[r]);
    }

    const int NC = H_ / 32;
    for (int c = 0; c < NC; c++) {
        #pragma unroll
        for (int r = 0; r < 2; r++) {
            float* da = &sA[arow[r] * 36 + acol[r]];
            da[0] = __uint_as_float(f2tf(va[r].x)); da[1] = __uint_as_float(f2tf(va[r].y));
            da[2] = __uint_as_float(f2tf(va[r].z)); da[3] = __uint_as_float(f2tf(va[r].w));
            float* dg = &sG[brow[r] * 68 + bcol[r]];
            dg[0] = __uint_as_float(f2tf(vg[r].x)); dg[1] = __uint_as_float(f2tf(vg[r].y));
            dg[2] = __uint_as_float(f2tf(vg[r].z)); dg[3] = __uint_as_float(f2tf(vg[r].w));
            float* du = &sU[brow[r] * 68 + bcol[r]];
            du[0] = __uint_as_float(f2tf(vu[r].x)); du[1] = __uint_as_float(f2tf(vu[r].y));
            du[2] = __uint_as_float(f2tf(vu[r].z)); du[3] = __uint_as_float(f2tf(vu[r].w));
        }
        __syncthreads();
        if (c + 1 < NC) {
            #pragma unroll
            for (int r = 0; r < 2; r++) {
                va[r] = *(const float4*)(aptr[r] + (size_t)(c+1) * 32);
                vg[r] = *(const float4*)(gptr[r] + (size_t)(c+1) * 32 * I_);
                vu[r] = *(const float4*)(uptr[r] + (size_t)(c+1) * 32 * I_);
            }
        }
        #pragma unroll
        for (int kk = 0; kk < 4; kk++) {
            int am = wm * 16 + ln4;
            uint32_t a0 = __float_as_uint(sA[am * 36 + kk*8 + lc]);
            uint32_t a1 = __float_as_uint(sA[(am+8) * 36 + kk*8 + lc]);
            uint32_t a2 = __float_as_uint(sA[am * 36 + kk*8 + lc + 4]);
            uint32_t a3 = __float_as_uint(sA[(am+8) * 36 + kk*8 + lc + 4]);
            int br = kk * 8 + lc;
            #pragma unroll
            for (int f = 0; f < 4; f++) {
                int bc = wn * 32 + f * 8 + ln4;
                uint32_t b0 = __float_as_uint(sG[br * 68 + bc]);
                uint32_t b1 = __float_as_uint(sG[(br+4) * 68 + bc]);
                mma_tf32(cg[f], a0, a1, a2, a3, b0, b1);
                uint32_t u0 = __float_as_uint(sU[br * 68 + bc]);
                uint32_t u1 = __float_as_uint(sU[(br+4) * 68 + bc]);
                mma_tf32(cu[f], a0, a1, a2, a3, u0, u1);
            }
        }
        __syncthreads();
    }

    #pragma unroll
    for (int f = 0; f < 4; f++)
        #pragma unroll
        for (int j = 0; j < 4; j++) {
            int row = wm * 16 + ln4 + ((j >> 1) ? 8 : 0);
            if (row < valid) {
                int col = i0 + wn * 32 + f * 8 + lc * 2 + (j & 1);
                float g = cg[f][j], u = cu[f][j];
                float a = u * (g / (1.f + expf(-g)));
                g_act[(size_t)(slot0 + row) * I_ + col] = a;
            }
        }
}

// ---------------- 6: grouped down GEMM (tf32) + weighted scatter-add ----------------
__global__ void __launch_bounds__(256) k_down(const float* __restrict__ wd,
                                              float* __restrict__ out) {
    int e  = blockIdx.z;
    int cnt = g_cnt[e];
    int mt = blockIdx.y;
    if (mt * 64 >= cnt) return;
    int h0 = blockIdx.x * 64;
    int slot0 = g_off[e] + mt * 64;
    int valid = cnt - mt * 64; if (valid > 64) valid = 64;

    __shared__ float sA[64 * 36];
    __shared__ float sB[32 * 68];

    int tid  = threadIdx.x;
    int lane = tid & 31, warp = tid >> 5;
    int wm = warp >> 1, wn = warp & 1;
    int ln4 = lane >> 2, lc = lane & 3;

    const float* aptr[2]; int arow[2], acol[2];
    const float* bptr[2]; int brow[2], bcol[2];
    #pragma unroll
    for (int r = 0; r < 2; r++) {
        int idx = tid + r * 256;
        int rowa = idx >> 3, c4a = idx & 7;
        aptr[r] = g_act + (size_t)(slot0 + rowa) * I_ + c4a * 4;
        arow[r] = rowa; acol[r] = c4a * 4;
        int rowb = idx >> 4, c4b = idx & 15;
        brow[r] = rowb; bcol[r] = c4b * 4;
        bptr[r] = wd + ((size_t)e * I_ + rowb) * H_ + h0 + c4b * 4;
    }

    float cd[4][4];
    #pragma unroll
    for (int f = 0; f < 4; f++)
        #pragma unroll
        for (int j = 0; j < 4; j++) cd[f][j] = 0.f;

    float4 va[2], vb[2];
    #pragma unroll
    for (int r = 0; r < 2; r++) {
        va[r] = *(const float4*)(aptr[r]);
        vb[r] = *(const float4*)(bptr[r]);
    }

    const int NC = I_ / 32;
    for (int c = 0; c < NC; c++) {
        #pragma unroll
        for (int r = 0; r < 2; r++) {
            float* da = &sA[arow[r] * 36 + acol[r]];
            da[0] = __uint_as_float(f2tf(va[r].x)); da[1] = __uint_as_float(f2tf(va[r].y));
            da[2] = __uint_as_float(f2tf(va[r].z)); da[3] = __uint_as_float(f2tf(va[r].w));
            float* db = &sB[brow[r] * 68 + bcol[r]];
            db[0] = __uint_as_float(f2tf(vb[r].x)); db[1] = __uint_as_float(f2tf(vb[r].y));
            db[2] = __uint_as_float(f2tf(vb[r].z)); db[3] = __uint_as_float(f2tf(vb[r].w));
        }
        __syncthreads();
        if (c + 1 < NC) {
            #pragma unroll
            for (int r = 0; r < 2; r++) {
                va[r] = *(const float4*)(aptr[r] + (size_t)(c+1) * 32);
                vb[r] = *(const float4*)(bptr[r] + (size_t)(c+1) * 32 * H_);
            }
        }
        #pragma unroll
        for (int kk = 0; kk < 4; kk++) {
            int am = wm * 16 + ln4;
            uint32_t a0 = __float_as_uint(sA[am * 36 + kk*8 + lc]);
            uint32_t a1 = __float_as_uint(sA[(am+8) * 36 + kk*8 + lc]);
            uint32_t a2 = __float_as_uint(sA[am * 36 + kk*8 + lc + 4]);
            uint32_t a3 = __float_as_uint(sA[(am+8) * 36 + kk*8 + lc + 4]);
            int br = kk * 8 + lc;
            #pragma unroll
            for (int f = 0; f < 4; f++) {
                int bc = wn * 32 + f * 8 + ln4;
                uint32_t b0 = __float_as_uint(sB[br * 68 + bc]);
                uint32_t b1 = __float_as_uint(sB[(br+4) * 68 + bc]);
                mma_tf32(cd[f], a0, a1, a2, a3, b0, b1);
            }
        }
        __syncthreads();
    }

    #pragma unroll
    for (int f = 0; f < 4; f++)
        #pragma unroll
        for (int j = 0; j < 4; j++) {
            int row = wm * 16 + ln4 + ((j >> 1) ? 8 : 0);
            if (row < valid) {
                int tok = g_tok[slot0 + row];
                float wt = g_wt[slot0 + row];
                int col = h0 + wn * 32 + f * 8 + lc * 2 + (j & 1);
                atomicAdd(&out[(size_t)tok * H_ + col], cd[f][j] * wt);
            }
        }
}

// ---------------- launch ----------------
extern "C" void kernel_launch(void* const* d_in, const int* in_sizes, int n_in,
                              void* d_out, int out_size) {
    const float* x  = (const float*)d_in[0];   // [T, H]
    const float* gw = (const float*)d_in[1];   // [E, H]
    const float* wg = (const float*)d_in[2];   // [E, H, I]
    const float* wu = (const float*)d_in[3];   // [E, H, I]
    const float* wd = (const float*)d_in[4];   // [E, I, H]
    float* out = (float*)d_out;                // [T, H]

    k_zero  <<<(T_*H_ + 255) / 256, 256>>>(out);
    k_router<<<T_ / 4, 256>>>(x, gw);
    k_topk  <<<(T_ + 255) / 256, 256>>>();
    k_scan  <<<1, 32>>>();
    k_fill  <<<(NSLOT + 255) / 256, 256>>>();
    k_gateup<<<dim3(I_/64, 16, E_), 256>>>(x, wg, wu);
    k_down  <<<dim3(H_/64, 16, E_), 256>>>(wd, out);
}

// round 11
// speedup vs baseline: 1.1207x; 1.1207x over previous
#include <cuda_runtime.h>
#include <cstdint>
#include <math.h>

#define T_ 1024
#define H_ 2048
#define E_ 64
#define KTOP 8
#define I_ 1024
#define NSLOT (T_*KTOP)

// ---------------- scratch (device globals) ----------------
__device__ float g_xs[T_*H_];           // x rounded-to-nearest at tf32 grid (low 13 bits dirty, MMA ignores)
__device__ float g_logits[T_*E_];
__device__ int   g_topk_idx[NSLOT];
__device__ float g_topk_wt[NSLOT];
__device__ int   g_cnt[E_];
__device__ int   g_off[E_];
__device__ int   g_cur[E_];
__device__ int   g_tok[NSLOT + 256];
__device__ float g_wt[NSLOT + 256];
__device__ float g_act[(size_t)(NSLOT + 256) * I_];   // pre-rounded for down GEMM

#define SWZ(o) ((uint32_t)(o) ^ ((((uint32_t)(o)) >> 3) & 0x70))
// round-to-nearest at the 13-bit truncation the tf32 MMA applies: +half-ulp (0x1000)
#define RND13(b) ((b) + 0x1000u)

__device__ __forceinline__ uint32_t smem_u32(const void* p) {
    uint32_t a;
    asm("{ .reg .u64 t; cvta.to.shared.u64 t, %1; cvt.u32.u64 %0, t; }" : "=r"(a) : "l"(p));
    return a;
}
__device__ __forceinline__ float rndf(float x) {
    return __uint_as_float(RND13(__float_as_uint(x)));
}

#define LDSM4(r0,r1,r2,r3,a) \
    asm volatile("ldmatrix.sync.aligned.m8n8.x4.shared.b16 {%0,%1,%2,%3}, [%4];" \
        : "=r"(r0), "=r"(r1), "=r"(r2), "=r"(r3) : "r"(a))

__device__ __forceinline__ void mma8(float* c, const uint32_t* a, uint32_t b0, uint32_t b1) {
    asm volatile(
        "mma.sync.aligned.m16n8k8.row.col.f32.tf32.tf32.f32 "
        "{%0,%1,%2,%3}, {%4,%5,%6,%7}, {%8,%9}, {%0,%1,%2,%3};\n"
        : "+f"(c[0]), "+f"(c[1]), "+f"(c[2]), "+f"(c[3])
        : "r"(a[0]), "r"(a[1]), "r"(a[2]), "r"(a[3]), "r"(b0), "r"(b1));
}

// ---------------- 0: zero output + counters + pre-round x ----------------
__global__ void k_zero(float* __restrict__ out, const float* __restrict__ x) {
    int i = blockIdx.x * blockDim.x + threadIdx.x;
    if (i < T_*H_) { out[i] = 0.f; g_xs[i] = rndf(x[i]); }
    if (i < E_) { g_cnt[i] = 0; g_cur[i] = 0; }
}

// ---------------- 1: router logits (fp32 exact) ----------------
__global__ void __launch_bounds__(256) k_router(const float* __restrict__ x,
                                                const float* __restrict__ gw) {
    __shared__ float xs[4 * H_];
    int t0 = blockIdx.x * 4;
    for (int i = threadIdx.x; i < 4 * H_; i += 256)
        xs[i] = x[(size_t)t0 * H_ + i];
    __syncthreads();
    int warp = threadIdx.x >> 5, lane = threadIdx.x & 31;
    for (int ei = 0; ei < 8; ei++) {
        int e = warp * 8 + ei;
        const float* w = gw + (size_t)e * H_;
        float a0 = 0.f, a1 = 0.f, a2 = 0.f, a3 = 0.f;
        for (int h = lane; h < H_; h += 32) {
            float wv = w[h];
            a0 = fmaf(wv, xs[h],        a0);
            a1 = fmaf(wv, xs[H_   + h], a1);
            a2 = fmaf(wv, xs[2*H_ + h], a2);
            a3 = fmaf(wv, xs[3*H_ + h], a3);
        }
        #pragma unroll
        for (int o = 16; o; o >>= 1) {
            a0 += __shfl_xor_sync(0xffffffffu, a0, o);
            a1 += __shfl_xor_sync(0xffffffffu, a1, o);
            a2 += __shfl_xor_sync(0xffffffffu, a2, o);
            a3 += __shfl_xor_sync(0xffffffffu, a3, o);
        }
        if (lane == 0) {
            g_logits[(t0+0)*E_ + e] = a0;
            g_logits[(t0+1)*E_ + e] = a1;
            g_logits[(t0+2)*E_ + e] = a2;
            g_logits[(t0+3)*E_ + e] = a3;
        }
    }
}

// ---------------- 2: softmax + top-8 + histogram ----------------
__global__ void k_topk() {
    int t = blockIdx.x * blockDim.x + threadIdx.x;
    if (t >= T_) return;
    float l[E_];
    const float* lg = g_logits + t * E_;
    float mx = -1e30f;
    for (int e = 0; e < E_; e++) { l[e] = lg[e]; mx = fmaxf(mx, l[e]); }
    float s = 0.f;
    for (int e = 0; e < E_; e++) { l[e] = expf(l[e] - mx); s += l[e]; }
    float inv = 1.f / s;
    for (int k = 0; k < KTOP; k++) {
        float best = -1.f; int be = 0;
        for (int e = 0; e < E_; e++)
            if (l[e] > best) { best = l[e]; be = e; }
        g_topk_idx[t*KTOP + k] = be;
        g_topk_wt [t*KTOP + k] = best * inv;
        l[be] = -1.f;
        atomicAdd(&g_cnt[be], 1);
    }
}

// ---------------- 3: scan ----------------
__global__ void k_scan() {
    if (threadIdx.x == 0) {
        int acc = 0;
        for (int e = 0; e < E_; e++) { g_off[e] = acc; acc += g_cnt[e]; }
    }
}

// ---------------- 4: slot fill ----------------
__global__ void k_fill() {
    int i = blockIdx.x * blockDim.x + threadIdx.x;
    if (i >= NSLOT) return;
    int t = i >> 3;
    int e = g_topk_idx[i];
    int pos = atomicAdd(&g_cur[e], 1);
    int slot = g_off[e] + pos;
    g_tok[slot] = t;
    g_wt [slot] = g_topk_wt[i];
}

// ---------------- 5: grouped gate/up GEMM, tf32 mma.sync ----------------
// Block: M=128 slots x N=64 i-cols (G and U). K chunk = 32. 8 warps = 4M x 2N, warp 32x32.
// Stage: A 16KB | G 8KB | U 8KB = 32KB, double-buffered = 64KB.
__global__ void __launch_bounds__(256) k_gateup(const float* __restrict__ wg,
                                                const float* __restrict__ wu) {
    extern __shared__ char smem[];
    const int e   = blockIdx.z;
    const int cnt = g_cnt[e];
    const int mtb = blockIdx.y;
    if (mtb * 128 >= cnt) return;
    const int i0    = blockIdx.x * 64;
    const int slot0 = g_off[e] + mtb * 128;
    int valid = cnt - mtb * 128; if (valid > 128) valid = 128;

    const int tid = threadIdx.x, lane = tid & 31, wid = tid >> 5;
    const int wm = wid & 3, wn = wid >> 2;
    const int wrow = wm * 32;
    const int g = lane >> 2, tg = lane & 3;
    const uint32_t sb = smem_u32(smem);

    // ---- fill descriptors ----
    int arow = tid >> 1, aseg = tid & 1;
    int atok = g_tok[slot0 + (arow < valid ? arow : 0)];
    const float4* aSrc = (const float4*)(g_xs + (size_t)atok * H_ + aseg * 16);
    uint32_t aoff[4];
    #pragma unroll
    for (int q = 0; q < 4; q++)
        aoff[q] = (uint32_t)(arow * 128) + (((uint32_t)(aseg * 64 + q * 16)) ^ ((uint32_t)(arow & 7) << 4));

    int bk = tid >> 4, bn4 = tid & 15;
    const uint4* gS = (const uint4*)(wg + (size_t)e * H_ * I_ + (size_t)bk * I_ + i0) + bn4;
    const uint4* uS = (const uint4*)(wu + (size_t)e * H_ * I_ + (size_t)bk * I_ + i0) + bn4;
    uint32_t boff[2];
    #pragma unroll
    for (int p = 0; p < 2; p++) { int k = p * 16 + bk; boff[p] = SWZ(k * 256 + bn4 * 16); }

    // ---- fragment address precompute ----
    const uint32_t aLdBase = (uint32_t)((wrow + (lane & 15)) * 128);
    const uint32_t aL16 = (uint32_t)((lane >> 4) * 16);
    const uint32_t aXor = (uint32_t)((lane & 7) << 4);
    const uint32_t swzB = (uint32_t)(((2 * tg + wn) & 7) << 4);
    uint32_t inrow[4];
    #pragma unroll
    for (int j = 0; j < 4; j++)
        inrow[j] = ((uint32_t)(wn * 128 + j * 32 + g * 4)) ^ swzB;

    float accG[2][4][4], accU[2][4][4];
    #pragma unroll
    for (int m = 0; m < 2; m++)
        #pragma unroll
        for (int j = 0; j < 4; j++)
            #pragma unroll
            for (int q = 0; q < 4; q++) { accG[m][j][q] = 0.f; accU[m][j][q] = 0.f; }

    float4 vA[4]; uint4 vG[2], vU[2];
    auto LOADC = [&](int c) {
        #pragma unroll
        for (int q = 0; q < 4; q++) vA[q] = aSrc[c * 8 + q];
        #pragma unroll
        for (int p = 0; p < 2; p++) {
            size_t o = (size_t)(c * 32 + p * 16) * (I_ / 4);
            vG[p] = gS[o]; vU[p] = uS[o];
        }
    };
    auto STORE = [&](int s) {
        char* A = smem + s * 32768;
        #pragma unroll
        for (int q = 0; q < 4; q++) *(float4*)(A + aoff[q]) = vA[q];   // A pre-rounded
        char* G = smem + s * 32768 + 16384;
        char* U = smem + s * 32768 + 24576;
        #pragma unroll
        for (int p = 0; p < 2; p++) {
            uint4 rg = make_uint4(RND13(vG[p].x), RND13(vG[p].y), RND13(vG[p].z), RND13(vG[p].w));
            *(uint4*)(G + boff[p]) = rg;
            uint4 ru = make_uint4(RND13(vU[p].x), RND13(vU[p].y), RND13(vU[p].z), RND13(vU[p].w));
            *(uint4*)(U + boff[p]) = ru;
        }
    };
    auto MMAS = [&](int s) {
        uint32_t As = sb + s * 32768;
        const char* Gs = smem + s * 32768 + 16384;
        const char* Us = smem + s * 32768 + 24576;
        #pragma unroll
        for (int kt = 0; kt < 4; kt++) {
            uint32_t a0[4], a1[4];
            uint32_t ao = As + aLdBase + (((uint32_t)(kt * 32) + aL16) ^ aXor);
            LDSM4(a0[0], a0[1], a0[2], a0[3], ao);
            LDSM4(a1[0], a1[1], a1[2], a1[3], ao + 2048);
            uint32_t bg[4][2], bu[4][2];
            #pragma unroll
            for (int j = 0; j < 4; j++)
                #pragma unroll
                for (int r = 0; r < 2; r++) {
                    uint32_t off = (uint32_t)((kt * 8 + tg + r * 4) * 256) + inrow[j];
                    bg[j][r] = *(const uint32_t*)(Gs + off);
                    bu[j][r] = *(const uint32_t*)(Us + off);
                }
            #pragma unroll
            for (int j = 0; j < 4; j++) {
                mma8(accG[0][j], a0, bg[j][0], bg[j][1]);
                mma8(accG[1][j], a1, bg[j][0], bg[j][1]);
                mma8(accU[0][j], a0, bu[j][0], bu[j][1]);
                mma8(accU[1][j], a1, bu[j][0], bu[j][1]);
            }
        }
    };

    LOADC(0); STORE(0); LOADC(1);
    __syncthreads();
    const int NC = H_ / 32;
    for (int c = 0; c < NC; c++) {
        MMAS(c & 1);
        __syncthreads();
        if (c + 1 < NC) {
            STORE((c + 1) & 1);
            if (c + 2 < NC) LOADC(c + 2);
            __syncthreads();
        }
    }

    // epilogue: act = silu(G)*U, written pre-rounded for the down GEMM's A operand
    #pragma unroll
    for (int m = 0; m < 2; m++) {
        int r0 = wrow + m * 16 + g, r1 = r0 + 8;
        #pragma unroll
        for (int j = 0; j < 4; j++) {
            int c0 = i0 + wn * 32 + j * 8 + tg * 2;
            if (r0 < valid) {
                float gg0 = accG[m][j][0], gg1 = accG[m][j][1];
                float2 o;
                o.x = rndf(accU[m][j][0] * (gg0 / (1.f + __expf(-gg0))));
                o.y = rndf(accU[m][j][1] * (gg1 / (1.f + __expf(-gg1))));
                *(float2*)(g_act + (size_t)(slot0 + r0) * I_ + c0) = o;
            }
            if (r1 < valid) {
                float gg2 = accG[m][j][2], gg3 = accG[m][j][3];
                float2 o;
                o.x = rndf(accU[m][j][2] * (gg2 / (1.f + __expf(-gg2))));
                o.y = rndf(accU[m][j][3] * (gg3 / (1.f + __expf(-gg3))));
                *(float2*)(g_act + (size_t)(slot0 + r1) * I_ + c0) = o;
            }
        }
    }
}

// ---------------- 6: grouped down GEMM, tf32 mma.sync + weighted scatter ----------------
// Block: M=128 slots x N=64 h-cols. K chunk = 32 over I. Stage: A 16KB | B 8KB = 24KB x2.
__global__ void __launch_bounds__(256) k_down(const float* __restrict__ wd,
                                              float* __restrict__ out) {
    extern __shared__ char smem[];
    const int e   = blockIdx.z;
    const int cnt = g_cnt[e];
    const int mtb = blockIdx.y;
    if (mtb * 128 >= cnt) return;
    const int h0    = blockIdx.x * 64;
    const int slot0 = g_off[e] + mtb * 128;
    int valid = cnt - mtb * 128; if (valid > 128) valid = 128;

    const int tid = threadIdx.x, lane = tid & 31, wid = tid >> 5;
    const int wm = wid & 3, wn = wid >> 2;
    const int wrow = wm * 32;
    const int g = lane >> 2, tg = lane & 3;
    const uint32_t sb = smem_u32(smem);

    int arow = tid >> 1, aseg = tid & 1;
    const float4* aSrc = (const float4*)(g_act + (size_t)(slot0 + arow) * I_ + aseg * 16);
    uint32_t aoff[4];
    #pragma unroll
    for (int q = 0; q < 4; q++)
        aoff[q] = (uint32_t)(arow * 128) + (((uint32_t)(aseg * 64 + q * 16)) ^ ((uint32_t)(arow & 7) << 4));

    int bk = tid >> 4, bn4 = tid & 15;
    const uint4* bS = (const uint4*)(wd + (size_t)e * I_ * H_ + (size_t)bk * H_ + h0) + bn4;
    uint32_t boff[2];
    #pragma unroll
    for (int p = 0; p < 2; p++) { int k = p * 16 + bk; boff[p] = SWZ(k * 256 + bn4 * 16); }

    const uint32_t aLdBase = (uint32_t)((wrow + (lane & 15)) * 128);
    const uint32_t aL16 = (uint32_t)((lane >> 4) * 16);
    const uint32_t aXor = (uint32_t)((lane & 7) << 4);
    const uint32_t swzB = (uint32_t)(((2 * tg + wn) & 7) << 4);
    uint32_t inrow[4];
    #pragma unroll
    for (int j = 0; j < 4; j++)
        inrow[j] = ((uint32_t)(wn * 128 + j * 32 + g * 4)) ^ swzB;

    float acc[2][4][4];
    #pragma unroll
    for (int m = 0; m < 2; m++)
        #pragma unroll
        for (int j = 0; j < 4; j++)
            #pragma unroll
            for (int q = 0; q < 4; q++) acc[m][j][q] = 0.f;

    float4 vA[4]; uint4 vB[2];
    auto LOADC = [&](int c) {
        #pragma unroll
        for (int q = 0; q < 4; q++) vA[q] = aSrc[c * 8 + q];
        #pragma unroll
        for (int p = 0; p < 2; p++)
            vB[p] = bS[(size_t)(c * 32 + p * 16) * (H_ / 4)];
    };
    auto STORE = [&](int s) {
        char* A = smem + s * 24576;
        #pragma unroll
        for (int q = 0; q < 4; q++) *(float4*)(A + aoff[q]) = vA[q];   // act pre-rounded
        char* B = smem + s * 24576 + 16384;
        #pragma unroll
        for (int p = 0; p < 2; p++) {
            uint4 rb = make_uint4(RND13(vB[p].x), RND13(vB[p].y), RND13(vB[p].z), RND13(vB[p].w));
            *(uint4*)(B + boff[p]) = rb;
        }
    };
    auto MMAS = [&](int s) {
        uint32_t As = sb + s * 24576;
        const char* Bs = smem + s * 24576 + 16384;
        #pragma unroll
        for (int kt = 0; kt < 4; kt++) {
            uint32_t a0[4], a1[4];
            uint32_t ao = As + aLdBase + (((uint32_t)(kt * 32) + aL16) ^ aXor);
            LDSM4(a0[0], a0[1], a0[2], a0[3], ao);
            LDSM4(a1[0], a1[1], a1[2], a1[3], ao + 2048);
            uint32_t bb[4][2];
            #pragma unroll
            for (int j = 0; j < 4; j++)
                #pragma unroll
                for (int r = 0; r < 2; r++) {
                    uint32_t off = (uint32_t)((kt * 8 + tg + r * 4) * 256) + inrow[j];
                    bb[j][r] = *(const uint32_t*)(Bs + off);
                }
            #pragma unroll
            for (int j = 0; j < 4; j++) {
                mma8(acc[0][j], a0, bb[j][0], bb[j][1]);
                mma8(acc[1][j], a1, bb[j][0], bb[j][1]);
            }
        }
    };

    LOADC(0); STORE(0); LOADC(1);
    __syncthreads();
    const int NC = I_ / 32;
    for (int c = 0; c < NC; c++) {
        MMAS(c & 1);
        __syncthreads();
        if (c + 1 < NC) {
            STORE((c + 1) & 1);
            if (c + 2 < NC) LOADC(c + 2);
            __syncthreads();
        }
    }

    // epilogue: weighted scatter-add
    #pragma unroll
    for (int m = 0; m < 2; m++) {
        int r0 = wrow + m * 16 + g, r1 = r0 + 8;
        int t0v = 0, t1v = 0; float w0 = 0.f, w1 = 0.f;
        if (r0 < valid) { t0v = g_tok[slot0 + r0]; w0 = g_wt[slot0 + r0]; }
        if (r1 < valid) { t1v = g_tok[slot0 + r1]; w1 = g_wt[slot0 + r1]; }
        #pragma unroll
        for (int j = 0; j < 4; j++) {
            int c0 = h0 + wn * 32 + j * 8 + tg * 2;
            if (r0 < valid) {
                atomicAdd(&out[(size_t)t0v * H_ + c0    ], acc[m][j][0] * w0);
                atomicAdd(&out[(size_t)t0v * H_ + c0 + 1], acc[m][j][1] * w0);
            }
            if (r1 < valid) {
                atomicAdd(&out[(size_t)t1v * H_ + c0    ], acc[m][j][2] * w1);
                atomicAdd(&out[(size_t)t1v * H_ + c0 + 1], acc[m][j][3] * w1);
            }
        }
    }
}

// ---------------- launch ----------------
extern "C" void kernel_launch(void* const* d_in, const int* in_sizes, int n_in,
                              void* d_out, int out_size) {
    const float* x  = (const float*)d_in[0];   // [T, H]
    const float* gw = (const float*)d_in[1];   // [E, H]
    const float* wg = (const float*)d_in[2];   // [E, H, I]
    const float* wu = (const float*)d_in[3];   // [E, H, I]
    const float* wd = (const float*)d_in[4];   // [E, I, H]
    float* out = (float*)d_out;                // [T, H]

    cudaFuncSetAttribute(k_gateup, cudaFuncAttributeMaxDynamicSharedMemorySize, 65536);
    cudaFuncSetAttribute(k_down,   cudaFuncAttributeMaxDynamicSharedMemorySize, 49152);

    k_zero  <<<(T_*H_ + 255) / 256, 256>>>(out, x);
    k_router<<<T_ / 4, 256>>>(x, gw);
    k_topk  <<<(T_ + 255) / 256, 256>>>();
    k_scan  <<<1, 32>>>();
    k_fill  <<<(NSLOT + 255) / 256, 256>>>();
    k_gateup<<<dim3(I_/64, 8, E_), 256, 65536>>>(wg, wu);
    k_down  <<<dim3(H_/64, 8, E_), 256, 49152>>>(wd, out);
}

// round 13
// speedup vs baseline: 1.3930x; 1.2429x over previous
#include <cuda_runtime.h>
#include <cstdint>
#include <math.h>

#define T_ 1024
#define H_ 2048
#define E_ 64
#define KTOP 8
#define I_ 1024
#define NSLOT (T_*KTOP)

// ---------------- scratch (device globals) ----------------
__device__ float g_xs[T_*H_];           // x rounded-to-nearest at tf32 grid
__device__ float g_logits[T_*E_];
__device__ int   g_topk_idx[NSLOT];
__device__ float g_topk_wt[NSLOT];
__device__ int   g_cnt[E_];
__device__ int   g_off[E_];
__device__ int   g_cur[E_];
__device__ int   g_tok[NSLOT + 256];
__device__ float g_wt[NSLOT + 256];
__device__ float g_act[(size_t)(NSLOT + 256) * I_];   // pre-rounded for down GEMM

#define SWZ(o) ((uint32_t)(o) ^ ((((uint32_t)(o)) >> 3) & 0x70))
// round-to-nearest at the 13-bit truncation the tf32 MMA applies: +half-ulp
#define RND13(b) ((b) + 0x1000u)

__device__ __forceinline__ uint32_t smem_u32(const void* p) {
    uint32_t a;
    asm("{ .reg .u64 t; cvta.to.shared.u64 t, %1; cvt.u32.u64 %0, t; }" : "=r"(a) : "l"(p));
    return a;
}
__device__ __forceinline__ float rndf(float x) {
    return __uint_as_float(RND13(__float_as_uint(x)));
}

#define CPA16(dst, src) \
    asm volatile("cp.async.cg.shared.global [%0], [%1], 16;" :: "r"(dst), "l"(src))
#define CPCOMMIT() asm volatile("cp.async.commit_group;" ::: "memory")
#define CPWAIT(n)  asm volatile("cp.async.wait_group %0;" :: "n"(n) : "memory")

#define LDSM4(r0,r1,r2,r3,a) \
    asm volatile("ldmatrix.sync.aligned.m8n8.x4.shared.b16 {%0,%1,%2,%3}, [%4];" \
        : "=r"(r0), "=r"(r1), "=r"(r2), "=r"(r3) : "r"(a))

__device__ __forceinline__ void mma8(float* c, const uint32_t* a, uint32_t b0, uint32_t b1) {
    asm volatile(
        "mma.sync.aligned.m16n8k8.row.col.f32.tf32.tf32.f32 "
        "{%0,%1,%2,%3}, {%4,%5,%6,%7}, {%8,%9}, {%0,%1,%2,%3};\n"
        : "+f"(c[0]), "+f"(c[1]), "+f"(c[2]), "+f"(c[3])
        : "r"(a[0]), "r"(a[1]), "r"(a[2]), "r"(a[3]), "r"(b0), "r"(b1));
}

// ---------------- 0: zero output + counters + pre-round x ----------------
__global__ void k_zero(float* __restrict__ out, const float* __restrict__ x) {
    int i = blockIdx.x * blockDim.x + threadIdx.x;
    if (i < T_*H_) { out[i] = 0.f; g_xs[i] = rndf(x[i]); }
    if (i < E_) { g_cnt[i] = 0; g_cur[i] = 0; }
}

// ---------------- 1: router logits (fp32 exact) ----------------
__global__ void __launch_bounds__(256) k_router(const float* __restrict__ x,
                                                const float* __restrict__ gw) {
    __shared__ float xs[4 * H_];
    int t0 = blockIdx.x * 4;
    for (int i = threadIdx.x; i < 4 * H_; i += 256)
        xs[i] = x[(size_t)t0 * H_ + i];
    __syncthreads();
    int warp = threadIdx.x >> 5, lane = threadIdx.x & 31;
    for (int ei = 0; ei < 8; ei++) {
        int e = warp * 8 + ei;
        const float* w = gw + (size_t)e * H_;
        float a0 = 0.f, a1 = 0.f, a2 = 0.f, a3 = 0.f;
        for (int h = lane; h < H_; h += 32) {
            float wv = w[h];
            a0 = fmaf(wv, xs[h],        a0);
            a1 = fmaf(wv, xs[H_   + h], a1);
            a2 = fmaf(wv, xs[2*H_ + h], a2);
            a3 = fmaf(wv, xs[3*H_ + h], a3);
        }
        #pragma unroll
        for (int o = 16; o; o >>= 1) {
            a0 += __shfl_xor_sync(0xffffffffu, a0, o);
            a1 += __shfl_xor_sync(0xffffffffu, a1, o);
            a2 += __shfl_xor_sync(0xffffffffu, a2, o);
            a3 += __shfl_xor_sync(0xffffffffu, a3, o);
        }
        if (lane == 0) {
            g_logits[(t0+0)*E_ + e] = a0;
            g_logits[(t0+1)*E_ + e] = a1;
            g_logits[(t0+2)*E_ + e] = a2;
            g_logits[(t0+3)*E_ + e] = a3;
        }
    }
}

// ---------------- 2: softmax + top-8 + histogram ----------------
__global__ void k_topk() {
    int t = blockIdx.x * blockDim.x + threadIdx.x;
    if (t >= T_) return;
    float l[E_];
    const float* lg = g_logits + t * E_;
    float mx = -1e30f;
    for (int e = 0; e < E_; e++) { l[e] = lg[e]; mx = fmaxf(mx, l[e]); }
    float s = 0.f;
    for (int e = 0; e < E_; e++) { l[e] = expf(l[e] - mx); s += l[e]; }
    float inv = 1.f / s;
    for (int k = 0; k < KTOP; k++) {
        float best = -1.f; int be = 0;
        for (int e = 0; e < E_; e++)
            if (l[e] > best) { best = l[e]; be = e; }
        g_topk_idx[t*KTOP + k] = be;
        g_topk_wt [t*KTOP + k] = best * inv;
        l[be] = -1.f;
        atomicAdd(&g_cnt[be], 1);
    }
}

// ---------------- 3: scan ----------------
__global__ void k_scan() {
    if (threadIdx.x == 0) {
        int acc = 0;
        for (int e = 0; e < E_; e++) { g_off[e] = acc; acc += g_cnt[e]; }
    }
}

// ---------------- 4: slot fill ----------------
__global__ void k_fill() {
    int i = blockIdx.x * blockDim.x + threadIdx.x;
    if (i >= NSLOT) return;
    int t = i >> 3;
    int e = g_topk_idx[i];
    int pos = atomicAdd(&g_cur[e], 1);
    int slot = g_off[e] + pos;
    g_tok[slot] = t;
    g_wt [slot] = g_topk_wt[i];
}

// ---------------- 5: grouped gate/up GEMM, cp.async pipeline + tf32 mma ----------------
// Block: M=128 slots x N=64 i-cols (G and U). K chunk = 32. 8 warps = 4M x 2N.
// 3 stages x (A 16KB | G 8KB | U 8KB) = 96KB dynamic smem, 2 blocks/SM.
// NOTE: one commit_group EVERY iteration (empty at tail) so wait_group<1>
// provably retires chunk c's group at iteration c — fixes R12 tail race.
__global__ void __launch_bounds__(256, 2) k_gateup(const float* __restrict__ wg,
                                                   const float* __restrict__ wu) {
    extern __shared__ char smem[];
    const int e   = blockIdx.z;
    const int cnt = g_cnt[e];
    const int mtb = blockIdx.y;
    if (mtb * 128 >= cnt) return;
    const int i0    = blockIdx.x * 64;
    const int slot0 = g_off[e] + mtb * 128;
    int valid = cnt - mtb * 128; if (valid > 128) valid = 128;

    const int tid = threadIdx.x, lane = tid & 31, wid = tid >> 5;
    const int wm = wid & 3, wn = wid >> 2;
    const int wrow = wm * 32;
    const int g = lane >> 2, tg = lane & 3;
    const uint32_t sb = smem_u32(smem);

    // ---- fill descriptors (per-thread, fixed) ----
    int arow = tid >> 1, aseg = tid & 1;
    int atok = g_tok[slot0 + (arow < valid ? arow : 0)];
    const float4* aSrc = (const float4*)(g_xs + (size_t)atok * H_ + aseg * 16);
    uint32_t aoff[4];
    #pragma unroll
    for (int q = 0; q < 4; q++)
        aoff[q] = (uint32_t)(arow * 128) + (((uint32_t)(aseg * 64 + q * 16)) ^ ((uint32_t)(arow & 7) << 4));

    int bk = tid >> 4, bn4 = tid & 15;
    const float4* gS = (const float4*)(wg + (size_t)e * H_ * I_ + (size_t)bk * I_ + i0) + bn4;
    const float4* uS = (const float4*)(wu + (size_t)e * H_ * I_ + (size_t)bk * I_ + i0) + bn4;
    uint32_t boff[2];
    #pragma unroll
    for (int p = 0; p < 2; p++) { int k = p * 16 + bk; boff[p] = SWZ(k * 256 + bn4 * 16); }

    // ---- fragment address precompute ----
    const uint32_t aLdBase = (uint32_t)((wrow + (lane & 15)) * 128);
    const uint32_t aL16 = (uint32_t)((lane >> 4) * 16);
    const uint32_t aXor = (uint32_t)((lane & 7) << 4);
    const uint32_t swzB = (uint32_t)(((2 * tg + wn) & 7) << 4);
    uint32_t inrow[4];
    #pragma unroll
    for (int j = 0; j < 4; j++)
        inrow[j] = ((uint32_t)(wn * 128 + j * 32 + g * 4)) ^ swzB;

    float accG[2][4][4], accU[2][4][4];
    #pragma unroll
    for (int m = 0; m < 2; m++)
        #pragma unroll
        for (int j = 0; j < 4; j++)
            #pragma unroll
            for (int q = 0; q < 4; q++) { accG[m][j][q] = 0.f; accU[m][j][q] = 0.f; }

    auto ISSUE = [&](int c) {
        int s = c % 3;
        uint32_t A = sb + s * 32768;
        #pragma unroll
        for (int q = 0; q < 4; q++) CPA16(A + aoff[q], aSrc + c * 8 + q);
        uint32_t G = sb + s * 32768 + 16384;
        uint32_t U = sb + s * 32768 + 24576;
        #pragma unroll
        for (int p = 0; p < 2; p++) {
            size_t o = (size_t)(c * 32 + p * 16) * (I_ / 4);
            CPA16(G + boff[p], gS + o);
            CPA16(U + boff[p], uS + o);
        }
    };
    auto MMAS = [&](int s) {
        uint32_t As = sb + s * 32768;
        const char* Gs = smem + s * 32768 + 16384;
        const char* Us = smem + s * 32768 + 24576;
        #pragma unroll
        for (int kt = 0; kt < 4; kt++) {
            uint32_t a0[4], a1[4];
            uint32_t ao = As + aLdBase + (((uint32_t)(kt * 32) + aL16) ^ aXor);
            LDSM4(a0[0], a0[1], a0[2], a0[3], ao);
            LDSM4(a1[0], a1[1], a1[2], a1[3], ao + 2048);
            uint32_t bg[4][2], bu[4][2];
            #pragma unroll
            for (int j = 0; j < 4; j++)
                #pragma unroll
                for (int r = 0; r < 2; r++) {
                    uint32_t off = (uint32_t)((kt * 8 + tg + r * 4) * 256) + inrow[j];
                    bg[j][r] = RND13(*(const uint32_t*)(Gs + off));
                    bu[j][r] = RND13(*(const uint32_t*)(Us + off));
                }
            #pragma unroll
            for (int j = 0; j < 4; j++) {
                mma8(accG[0][j], a0, bg[j][0], bg[j][1]);
                mma8(accG[1][j], a1, bg[j][0], bg[j][1]);
                mma8(accU[0][j], a0, bu[j][0], bu[j][1]);
                mma8(accU[1][j], a1, bu[j][0], bu[j][1]);
            }
        }
    };

    ISSUE(0); CPCOMMIT();
    ISSUE(1); CPCOMMIT();
    const int NC = H_ / 32;
    for (int c = 0; c < NC; c++) {
        CPWAIT(1);
        __syncthreads();
        if (c + 2 < NC) ISSUE(c + 2);
        CPCOMMIT();                         // unconditional: keeps group count exact at tail
        MMAS(c % 3);
    }

    // epilogue: act = silu(G)*U, written pre-rounded for the down GEMM
    #pragma unroll
    for (int m = 0; m < 2; m++) {
        int r0 = wrow + m * 16 + g, r1 = r0 + 8;
        #pragma unroll
        for (int j = 0; j < 4; j++) {
            int c0 = i0 + wn * 32 + j * 8 + tg * 2;
            if (r0 < valid) {
                float gg0 = accG[m][j][0], gg1 = accG[m][j][1];
                float2 o;
                o.x = rndf(accU[m][j][0] * (gg0 / (1.f + __expf(-gg0))));
                o.y = rndf(accU[m][j][1] * (gg1 / (1.f + __expf(-gg1))));
                *(float2*)(g_act + (size_t)(slot0 + r0) * I_ + c0) = o;
            }
            if (r1 < valid) {
                float gg2 = accG[m][j][2], gg3 = accG[m][j][3];
                float2 o;
                o.x = rndf(accU[m][j][2] * (gg2 / (1.f + __expf(-gg2))));
                o.y = rndf(accU[m][j][3] * (gg3 / (1.f + __expf(-gg3))));
                *(float2*)(g_act + (size_t)(slot0 + r1) * I_ + c0) = o;
            }
        }
    }
}

// ---------------- 6: grouped down GEMM, cp.async pipeline + tf32 mma + scatter ----------------
// Block: M=128 slots x N=64 h-cols. 4 stages x (A 16KB | B 8KB) = 96KB, 2 blocks/SM.
__global__ void __launch_bounds__(256, 2) k_down(const float* __restrict__ wd,
                                                 float* __restrict__ out) {
    extern __shared__ char smem[];
    const int e   = blockIdx.z;
    const int cnt = g_cnt[e];
    const int mtb = blockIdx.y;
    if (mtb * 128 >= cnt) return;
    const int h0    = blockIdx.x * 64;
    const int slot0 = g_off[e] + mtb * 128;
    int valid = cnt - mtb * 128; if (valid > 128) valid = 128;

    const int tid = threadIdx.x, lane = tid & 31, wid = tid >> 5;
    const int wm = wid & 3, wn = wid >> 2;
    const int wrow = wm * 32;
    const int g = lane >> 2, tg = lane & 3;
    const uint32_t sb = smem_u32(smem);

    int arow = tid >> 1, aseg = tid & 1;
    const float4* aSrc = (const float4*)(g_act + (size_t)(slot0 + arow) * I_ + aseg * 16);
    uint32_t aoff[4];
    #pragma unroll
    for (int q = 0; q < 4; q++)
        aoff[q] = (uint32_t)(arow * 128) + (((uint32_t)(aseg * 64 + q * 16)) ^ ((uint32_t)(arow & 7) << 4));

    int bk = tid >> 4, bn4 = tid & 15;
    const float4* bS = (const float4*)(wd + (size_t)e * I_ * H_ + (size_t)bk * H_ + h0) + bn4;
    uint32_t boff[2];
    #pragma unroll
    for (int p = 0; p < 2; p++) { int k = p * 16 + bk; boff[p] = SWZ(k * 256 + bn4 * 16); }

    const uint32_t aLdBase = (uint32_t)((wrow + (lane & 15)) * 128);
    const uint32_t aL16 = (uint32_t)((lane >> 4) * 16);
    const uint32_t aXor = (uint32_t)((lane & 7) << 4);
    const uint32_t swzB = (uint32_t)(((2 * tg + wn) & 7) << 4);
    uint32_t inrow[4];
    #pragma unroll
    for (int j = 0; j < 4; j++)
        inrow[j] = ((uint32_t)(wn * 128 + j * 32 + g * 4)) ^ swzB;

    float acc[2][4][4];
    #pragma unroll
    for (int m = 0; m < 2; m++)
        #pragma unroll
        for (int j = 0; j < 4; j++)
            #pragma unroll
            for (int q = 0; q < 4; q++) acc[m][j][q] = 0.f;

    auto ISSUE = [&](int c) {
        int s = c & 3;
        uint32_t A = sb + s * 24576;
        #pragma unroll
        for (int q = 0; q < 4; q++) CPA16(A + aoff[q], aSrc + c * 8 + q);
        uint32_t B = sb + s * 24576 + 16384;
        #pragma unroll
        for (int p = 0; p < 2; p++)
            CPA16(B + boff[p], bS + (size_t)(c * 32 + p * 16) * (H_ / 4));
    };
    auto MMAS = [&](int s) {
        uint32_t As = sb + s * 24576;
        const char* Bs = smem + s * 24576 + 16384;
        #pragma unroll
        for (int kt = 0; kt < 4; kt++) {
            uint32_t a0[4], a1[4];
            uint32_t ao = As + aLdBase + (((uint32_t)(kt * 32) + aL16) ^ aXor);
            LDSM4(a0[0], a0[1], a0[2], a0[3], ao);
            LDSM4(a1[0], a1[1], a1[2], a1[3], ao + 2048);
            uint32_t bb[4][2];
            #pragma unroll
            for (int j = 0; j < 4; j++)
                #pragma unroll
                for (int r = 0; r < 2; r++) {
                    uint32_t off = (uint32_t)((kt * 8 + tg + r * 4) * 256) + inrow[j];
                    bb[j][r] = RND13(*(const uint32_t*)(Bs + off));
                }
            #pragma unroll
            for (int j = 0; j < 4; j++) {
                mma8(acc[0][j], a0, bb[j][0], bb[j][1]);
                mma8(acc[1][j], a1, bb[j][0], bb[j][1]);
            }
        }
    };

    ISSUE(0); CPCOMMIT();
    ISSUE(1); CPCOMMIT();
    ISSUE(2); CPCOMMIT();
    const int NC = I_ / 32;
    for (int c = 0; c < NC; c++) {
        CPWAIT(2);
        __syncthreads();
        if (c + 3 < NC) ISSUE(c + 3);
        CPCOMMIT();                         // unconditional: keeps group count exact at tail
        MMAS(c & 3);
    }

    // epilogue: weighted scatter-add
    #pragma unroll
    for (int m = 0; m < 2; m++) {
        int r0 = wrow + m * 16 + g, r1 = r0 + 8;
        int t0v = 0, t1v = 0; float w0 = 0.f, w1 = 0.f;
        if (r0 < valid) { t0v = g_tok[slot0 + r0]; w0 = g_wt[slot0 + r0]; }
        if (r1 < valid) { t1v = g_tok[slot0 + r1]; w1 = g_wt[slot0 + r1]; }
        #pragma unroll
        for (int j = 0; j < 4; j++) {
            int c0 = h0 + wn * 32 + j * 8 + tg * 2;
            if (r0 < valid) {
                atomicAdd(&out[(size_t)t0v * H_ + c0    ], acc[m][j][0] * w0);
                atomicAdd(&out[(size_t)t0v * H_ + c0 + 1], acc[m][j][1] * w0);
            }
            if (r1 < valid) {
                atomicAdd(&out[(size_t)t1v * H_ + c0    ], acc[m][j][2] * w1);
                atomicAdd(&out[(size_t)t1v * H_ + c0 + 1], acc[m][j][3] * w1);
            }
        }
    }
}

// ---------------- launch ----------------
extern "C" void kernel_launch(void* const* d_in, const int* in_sizes, int n_in,
                              void* d_out, int out_size) {
    const float* x  = (const float*)d_in[0];   // [T, H]
    const float* gw = (const float*)d_in[1];   // [E, H]
    const float* wg = (const float*)d_in[2];   // [E, H, I]
    const float* wu = (const float*)d_in[3];   // [E, H, I]
    const float* wd = (const float*)d_in[4];   // [E, I, H]
    float* out = (float*)d_out;                // [T, H]

    cudaFuncSetAttribute(k_gateup, cudaFuncAttributeMaxDynamicSharedMemorySize, 98304);
    cudaFuncSetAttribute(k_down,   cudaFuncAttributeMaxDynamicSharedMemorySize, 98304);

    k_zero  <<<(T_*H_ + 255) / 256, 256>>>(out, x);
    k_router<<<T_ / 4, 256>>>(x, gw);
    k_topk  <<<(T_ + 255) / 256, 256>>>();
    k_scan  <<<1, 32>>>();
    k_fill  <<<(NSLOT + 255) / 256, 256>>>();
    k_gateup<<<dim3(I_/64, 8, E_), 256, 98304>>>(wg, wu);
    k_down  <<<dim3(H_/64, 8, E_), 256, 98304>>>(wd, out);
}